// round 2
// baseline (speedup 1.0000x reference)
#include <cuda_runtime.h>

// ---------------------------------------------------------------------------
// PTAttention3D  (B=2, C=128, T=4, H=W=64, heads=32, d=4, patch 4x4)
// N = T*h*w = 4*16*16 = 1024 tokens, P = 16 pixels/patch, table = 7*31*31 = 6727
//
// Pipeline:
//   k_zero    : zero Gram accumulator
//   k_pool    : xp[b][c][n]  = patch means of x  (pool commutes with conv+affine)
//   k_xbar    : xbar[b][c]   = global channel means
//   k_gram    : S[b] = sum_s x x^T   (for GroupNorm variance:  E[z^2] = w^T S w / S_cnt)
//   k_gnconst : per (proj,b,channel) scale/bias implementing GroupNorm affine
//   k_qkproj  : pooled Q,K projection + GN affine  -> g_Qn, g_Kn  [bg][n][4]
//   k_vproj   : full-res V projection + GN affine  -> g_Vn       [bg][m][64] (dd*16+p)
//   k_attn    : fused attention (no max needed: logits bounded), bias table in smem
// ---------------------------------------------------------------------------

__device__ float g_xp[2 * 128 * 1024];
__device__ float g_xbar[256];
__device__ float g_S[2 * 128 * 128];
__device__ float g_gnsc[3 * 2 * 128];
__device__ float g_gnbi[3 * 2 * 128];
__device__ float g_Qn[2 * 32 * 1024 * 4];
__device__ float g_Kn[2 * 32 * 1024 * 4];
__device__ float g_Vn[2 * 32 * 1024 * 64];

// ---------------------------------------------------------------------------
__global__ void k_zero() {
    int i = blockIdx.x * 1024 + threadIdx.x;
    if (i < 2 * 128 * 128) g_S[i] = 0.f;
}

// ---------------------------------------------------------------------------
// xp[b][c][n] = (1/16) * sum over 4x4 pixel patch
__global__ void __launch_bounds__(256) k_pool(const float* __restrict__ x) {
    int idx = blockIdx.x * 256 + threadIdx.x;          // 2*128*1024 = 262144
    int n = idx & 1023;
    int c = (idx >> 10) & 127;
    int b = idx >> 17;
    int t = n >> 8, hy = (n >> 4) & 15, wx = n & 15;
    const float* p = x + (((b * 128 + c) * 4 + t) * 4096) + (hy * 4) * 64 + wx * 4;
    float s = 0.f;
#pragma unroll
    for (int r = 0; r < 4; ++r) {
        float4 v = *(const float4*)(p + r * 64);
        s += v.x + v.y + v.z + v.w;
    }
    g_xp[idx] = s * (1.f / 16.f);
}

// ---------------------------------------------------------------------------
__global__ void __launch_bounds__(256) k_xbar() {
    int tid = threadIdx.x;                              // 256 = (b,c)
    const float* row = g_xp + tid * 1024;
    float s0 = 0.f, s1 = 0.f, s2 = 0.f, s3 = 0.f;
    for (int n = 0; n < 1024; n += 4) {
        s0 += row[n]; s1 += row[n + 1]; s2 += row[n + 2]; s3 += row[n + 3];
    }
    g_xbar[tid] = (s0 + s1 + s2 + s3) * (1.f / 1024.f);
}

// ---------------------------------------------------------------------------
// Gram: S[b][ci][cj] += sum over 256 spatial positions of x_ci * x_cj
// grid = b(2) x schunk(64), 256 threads (16x16), 8x8 micro-tile
__global__ void __launch_bounds__(256) k_gram(const float* __restrict__ x) {
    __shared__ __align__(16) float xs[128][65];
    int b = blockIdx.x >> 6;
    int s0 = (blockIdx.x & 63) * 256;
    int ty = threadIdx.x >> 4, tx = threadIdx.x & 15;
    float acc[8][8];
#pragma unroll
    for (int u = 0; u < 8; ++u)
#pragma unroll
        for (int v = 0; v < 8; ++v) acc[u][v] = 0.f;

    for (int sub = 0; sub < 4; ++sub) {
        __syncthreads();
        for (int i = threadIdx.x; i < 128 * 64; i += 256) {
            int c = i >> 6, ss = i & 63;
            xs[c][ss] = x[(b * 128 + c) * 16384 + s0 + sub * 64 + ss];
        }
        __syncthreads();
        for (int ss = 0; ss < 64; ++ss) {
            float a[8], bb[8];
#pragma unroll
            for (int u = 0; u < 8; ++u) a[u] = xs[ty * 8 + u][ss];
#pragma unroll
            for (int v = 0; v < 8; ++v) bb[v] = xs[tx * 8 + v][ss];
#pragma unroll
            for (int u = 0; u < 8; ++u)
#pragma unroll
                for (int v = 0; v < 8; ++v) acc[u][v] = fmaf(a[u], bb[v], acc[u][v]);
        }
    }
#pragma unroll
    for (int u = 0; u < 8; ++u)
#pragma unroll
        for (int v = 0; v < 8; ++v)
            atomicAdd(&g_S[(b * 128 + ty * 8 + u) * 128 + tx * 8 + v], acc[u][v]);
}

// ---------------------------------------------------------------------------
// GN constants per (proj, b, group):  mu = mean(W x),  E[z^2] = w^T S w / cnt
// grid = 192 (proj*2*32), 128 threads
__global__ void __launch_bounds__(128) k_gnconst(
    const float* __restrict__ Wq, const float* __restrict__ Wk, const float* __restrict__ Wv,
    const float* __restrict__ gqg, const float* __restrict__ gqb,
    const float* __restrict__ gkg, const float* __restrict__ gkb,
    const float* __restrict__ gvg, const float* __restrict__ gvb) {
    int pidx = blockIdx.x >> 6;           // 0=q 1=k 2=v
    int b = (blockIdx.x >> 5) & 1;
    int g = blockIdx.x & 31;
    const float* W   = pidx == 0 ? Wq  : (pidx == 1 ? Wk  : Wv);
    const float* gam = pidx == 0 ? gqg : (pidx == 1 ? gkg : gvg);
    const float* bet = pidx == 0 ? gqb : (pidx == 1 ? gkb : gvb);

    int i = threadIdx.x;
    float xb = g_xbar[b * 128 + i];
    float musum = 0.f;
    float accd[4] = {0.f, 0.f, 0.f, 0.f};
#pragma unroll
    for (int dd = 0; dd < 4; ++dd) musum += W[(g * 4 + dd) * 128 + i] * xb;

    const float* srow = g_S + (b * 128 + i) * 128;
    for (int j = 0; j < 128; ++j) {
        float sv = srow[j];
#pragma unroll
        for (int dd = 0; dd < 4; ++dd) accd[dd] = fmaf(sv, W[(g * 4 + dd) * 128 + j], accd[dd]);
    }
    float qsum = 0.f;
#pragma unroll
    for (int dd = 0; dd < 4; ++dd) qsum += W[(g * 4 + dd) * 128 + i] * accd[dd];

    __shared__ float r1[128], r2[128];
    __shared__ float s_mu, s_rs;
    r1[i] = musum; r2[i] = qsum;
    __syncthreads();
    for (int off = 64; off; off >>= 1) {
        if (i < off) { r1[i] += r1[i + off]; r2[i] += r2[i + off]; }
        __syncthreads();
    }
    if (i == 0) {
        float mu  = r1[0] * 0.25f;
        float ez2 = r2[0] * (1.f / (4.f * 16384.f));
        float var = ez2 - mu * mu;
        s_mu = mu;
        s_rs = rsqrtf(var + 1e-5f);
    }
    __syncthreads();
    if (i < 4) {
        int o = g * 4 + i;
        float sc = s_rs * gam[o];
        g_gnsc[(pidx * 2 + b) * 128 + o] = sc;
        g_gnbi[(pidx * 2 + b) * 128 + o] = bet[o] - s_mu * sc;
    }
}

// ---------------------------------------------------------------------------
// Pooled Q/K projection + GN affine.  grid = b(2) x nchunk(32), 256 threads.
// thread = output channel (0..127 -> Q, 128..255 -> K); 32 tokens per block.
__global__ void __launch_bounds__(256) k_qkproj(const float* __restrict__ Wq,
                                                const float* __restrict__ Wk) {
    __shared__ __align__(16) float xs[128][32];        // xs[c][n]
    int b = blockIdx.x >> 5;
    int n0 = (blockIdx.x & 31) * 32;
    int tid = threadIdx.x;
    for (int i = tid; i < 4096; i += 256) {
        int c = i >> 5, j = i & 31;
        xs[c][j] = g_xp[(b * 128 + c) * 1024 + n0 + j];
    }
    __syncthreads();

    int p = tid >> 7;
    int o = tid & 127;
    const float* Wrow = (p == 0 ? Wq : Wk) + o * 128;
    float4 acc[8];
#pragma unroll
    for (int i = 0; i < 8; ++i) acc[i] = make_float4(0.f, 0.f, 0.f, 0.f);

    for (int c = 0; c < 128; c += 4) {
        float4 w4 = *(const float4*)(Wrow + c);
        float wv[4] = {w4.x, w4.y, w4.z, w4.w};
#pragma unroll
        for (int s = 0; s < 4; ++s) {
            float w = wv[s];
            const float4* xr = (const float4*)&xs[c + s][0];
#pragma unroll
            for (int n4 = 0; n4 < 8; ++n4) {
                float4 xv = xr[n4];
                acc[n4].x = fmaf(w, xv.x, acc[n4].x);
                acc[n4].y = fmaf(w, xv.y, acc[n4].y);
                acc[n4].z = fmaf(w, xv.z, acc[n4].z);
                acc[n4].w = fmaf(w, xv.w, acc[n4].w);
            }
        }
    }
    float sc = g_gnsc[(p * 2 + b) * 128 + o];
    float bo = g_gnbi[(p * 2 + b) * 128 + o];
    int g = o >> 2, dd = o & 3;
    float* dst = (p == 0 ? g_Qn : g_Kn) + ((b * 32 + g) * 1024 + n0) * 4 + dd;
    float a[32];
#pragma unroll
    for (int n4 = 0; n4 < 8; ++n4) {
        a[n4 * 4 + 0] = acc[n4].x; a[n4 * 4 + 1] = acc[n4].y;
        a[n4 * 4 + 2] = acc[n4].z; a[n4 * 4 + 3] = acc[n4].w;
    }
#pragma unroll
    for (int nn = 0; nn < 32; ++nn) dst[nn * 4] = fmaf(a[nn], sc, bo);
}

// ---------------------------------------------------------------------------
// Full-res V projection + GN affine + layout  Vn[bg][m][dd*16+p]
// grid = b(2) x t(4) x yblk(16) = 128 CTAs, 256 threads.
// Each CTA: 256 positions (4 rows x 64 cols) x 128 output channels.
__global__ void __launch_bounds__(256) k_vproj(const float* __restrict__ x,
                                               const float* __restrict__ Wv) {
    __shared__ __align__(16) float xs[32][256];        // xs[c_local][pos]
    __shared__ float ws[32][33];                       // ws[oc_local][cc]
    int bi = blockIdx.x;
    int b = bi >> 6;
    int t = (bi >> 4) & 3;
    int yb = bi & 15;
    int tid = threadIdx.x;
    int pos0 = (tid & 63) << 2;
    int ocb = tid >> 6;                                // 0..3

    float acc[4][4][8];
#pragma unroll
    for (int a = 0; a < 4; ++a)
#pragma unroll
        for (int i = 0; i < 4; ++i)
#pragma unroll
            for (int j = 0; j < 8; ++j) acc[a][i][j] = 0.f;

    const float* xbase = x + ((b * 128) * 4 + t) * 4096 + (yb * 4) * 64;

    for (int ck = 0; ck < 4; ++ck) {
        __syncthreads();
        for (int i = tid; i < 32 * 256; i += 256) {
            int cl = i >> 8, posl = i & 255;
            xs[cl][posl] = xbase[(ck * 32 + cl) * 16384 + posl];
        }
#pragma unroll
        for (int og = 0; og < 4; ++og) {
            __syncthreads();
            for (int i = tid; i < 1024; i += 256) {
                int ocl = i >> 5, cc = i & 31;
                ws[ocl][cc] = Wv[(og * 32 + ocl) * 128 + ck * 32 + cc];
            }
            __syncthreads();
            for (int cc = 0; cc < 32; ++cc) {
                float4 a4 = *(const float4*)&xs[cc][pos0];
#pragma unroll
                for (int j = 0; j < 8; ++j) {
                    float w = ws[ocb * 8 + j][cc];
                    acc[og][0][j] = fmaf(a4.x, w, acc[og][0][j]);
                    acc[og][1][j] = fmaf(a4.y, w, acc[og][1][j]);
                    acc[og][2][j] = fmaf(a4.z, w, acc[og][2][j]);
                    acc[og][3][j] = fmaf(a4.w, w, acc[og][3][j]);
                }
            }
        }
    }

#pragma unroll
    for (int og = 0; og < 4; ++og) {
#pragma unroll
        for (int j = 0; j < 8; ++j) {
            int o = og * 32 + ocb * 8 + j;
            float sc = g_gnsc[(2 * 2 + b) * 128 + o];
            float bo = g_gnbi[(2 * 2 + b) * 128 + o];
            int g = o >> 2, dd = o & 3;
            float* vb = g_Vn + ((b * 32 + g) * 1024) * 64 + dd * 16;
#pragma unroll
            for (int i = 0; i < 4; ++i) {
                int pos = pos0 + i;
                int r = pos >> 6, xx = pos & 63;
                int n = (t * 16 + yb) * 16 + (xx >> 2);
                int p = r * 4 + (xx & 3);
                vb[n * 64 + p] = fmaf(acc[og][i][j], sc, bo);
            }
        }
    }
}

// ---------------------------------------------------------------------------
// Fused attention.  grid = b(2) x g(32) x ntile(8) = 512 CTAs, 128 threads.
// Thread = one query row. No running max (logits bounded well below exp range).
__global__ void __launch_bounds__(128) k_attn(const float* __restrict__ tab,
                                              const int* __restrict__ ridx,
                                              float* __restrict__ out) {
    __shared__ float sTab[6727];
    __shared__ float4 sK[64];
    __shared__ float4 sV[1024];                        // 64 keys x 16 float4 (64 floats)
    int bid = blockIdx.x;
    int nt = bid & 7, g = (bid >> 3) & 31, b = bid >> 8;
    int bg = b * 32 + g;
    int tid = threadIdx.x;

    for (int i = tid; i < 6727; i += 128) sTab[i] = tab[g * 6727 + i];

    int n = nt * 128 + tid;
    float4 q = ((const float4*)g_Qn)[bg * 1024 + n];
    float qx = q.x * 0.5f, qy = q.y * 0.5f, qz = q.z * 0.5f, qw = q.w * 0.5f;

    float acc[64];
#pragma unroll
    for (int i = 0; i < 64; ++i) acc[i] = 0.f;
    float l = 0.f;

    const int4* idxp = (const int4*)(ridx + (size_t)n * 1024);

    for (int m0 = 0; m0 < 1024; m0 += 64) {
        __syncthreads();
        if (tid < 64) sK[tid] = ((const float4*)g_Kn)[bg * 1024 + m0 + tid];
        const float4* vsrc = ((const float4*)g_Vn) + ((size_t)bg * 1024 + m0) * 16;
        for (int i = tid; i < 1024; i += 128) sV[i] = vsrc[i];
        __syncthreads();

#pragma unroll 1
        for (int mq = 0; mq < 16; ++mq) {
            int4 iv = idxp[(m0 >> 2) + mq];
            int ids[4] = {iv.x, iv.y, iv.z, iv.w};
#pragma unroll
            for (int u = 0; u < 4; ++u) {
                int mm = mq * 4 + u;
                float4 kk = sK[mm];
                float s = sTab[ids[u]];
                s = fmaf(qx, kk.x, s);
                s = fmaf(qy, kk.y, s);
                s = fmaf(qz, kk.z, s);
                s = fmaf(qw, kk.w, s);
                float e = __expf(s);
                l += e;
                const float4* vr = sV + mm * 16;
#pragma unroll
                for (int d4 = 0; d4 < 16; ++d4) {
                    float4 vv = vr[d4];
                    acc[d4 * 4 + 0] = fmaf(e, vv.x, acc[d4 * 4 + 0]);
                    acc[d4 * 4 + 1] = fmaf(e, vv.y, acc[d4 * 4 + 1]);
                    acc[d4 * 4 + 2] = fmaf(e, vv.z, acc[d4 * 4 + 2]);
                    acc[d4 * 4 + 3] = fmaf(e, vv.w, acc[d4 * 4 + 3]);
                }
            }
        }
    }

    float inv = 1.0f / l;
    int t = n >> 8, hy = (n >> 4) & 15, wx = n & 15;
#pragma unroll
    for (int dd = 0; dd < 4; ++dd) {
        float* ob = out + (((b * 128 + g * 4 + dd) * 4 + t) * 4096);
#pragma unroll
        for (int pp = 0; pp < 16; ++pp) {
            int y = hy * 4 + (pp >> 2);
            int xx = wx * 4 + (pp & 3);
            ob[y * 64 + xx] = acc[dd * 16 + pp] * inv;
        }
    }
}

// ---------------------------------------------------------------------------
extern "C" void kernel_launch(void* const* d_in, const int* in_sizes, int n_in,
                              void* d_out, int out_size) {
    const float* x   = (const float*)d_in[0];
    const float* Wq  = (const float*)d_in[1];
    const float* Wk  = (const float*)d_in[2];
    const float* Wv  = (const float*)d_in[3];
    const float* gqg = (const float*)d_in[4];
    const float* gqb = (const float*)d_in[5];
    const float* gkg = (const float*)d_in[6];
    const float* gkb = (const float*)d_in[7];
    const float* gvg = (const float*)d_in[8];
    const float* gvb = (const float*)d_in[9];
    const float* tab = (const float*)d_in[10];
    const int*   ri  = (const int*)d_in[11];
    float* out = (float*)d_out;

    k_zero<<<32, 1024>>>();
    k_pool<<<1024, 256>>>(x);
    k_xbar<<<1, 256>>>();
    k_gram<<<128, 256>>>(x);
    k_gnconst<<<192, 128>>>(Wq, Wk, Wv, gqg, gqb, gkg, gkb, gvg, gvb);
    k_qkproj<<<64, 256>>>(Wq, Wk);
    k_vproj<<<128, 256>>>(x, Wv);
    k_attn<<<512, 128>>>(tab, ri, out);
}

// round 3
// speedup vs baseline: 1.1668x; 1.1668x over previous
#include <cuda_runtime.h>

// ---------------------------------------------------------------------------
// PTAttention3D  (B=2, C=128, T=4, H=W=64, heads=32, d=4, patch 4x4)
// N = 1024 tokens, P = 16 pixels/patch, table = 7*31*31 = 6727
//
//   k_zero    : zero Gram + channel-sum accumulators
//   k_pool    : xp[b][c][n]  = patch means of x
//   k_gram    : S[b] = sum_s x x^T  AND  xsum[b][c] = sum_s x   (f32x2 FMA)
//   k_gnconst : per (proj,b,channel) GN scale/bias (Q gets 1/sqrt(d) folded in)
//   k_qkproj  : pooled Q,K projection + GN affine  -> g_Qn, g_Kn  [bg][n][4]
//   k_vproj   : full-res V projection + GN affine  -> g_Vn [bg][m][64]
//   k_attn    : fused attention, f32x2 packed AV accumulation
// ---------------------------------------------------------------------------

__device__ float g_xp[2 * 128 * 1024];
__device__ float g_xsum[256];
__device__ float g_S[2 * 128 * 128];
__device__ float g_gnsc[3 * 2 * 128];
__device__ float g_gnbi[3 * 2 * 128];
__device__ float g_Qn[2 * 32 * 1024 * 4];
__device__ float g_Kn[2 * 32 * 1024 * 4];
__device__ float g_Vn[2 * 32 * 1024 * 64];

// ---- packed f32x2 helpers (FFMA2: ptxas never emits it from C++) ----------
__device__ __forceinline__ unsigned long long dup2(float x) {
    unsigned long long r; unsigned u = __float_as_uint(x);
    asm("mov.b64 %0, {%1, %1};" : "=l"(r) : "r"(u));
    return r;
}
__device__ __forceinline__ unsigned long long fma2(unsigned long long a,
                                                   unsigned long long b,
                                                   unsigned long long c) {
    unsigned long long d;
    asm("fma.rn.f32x2 %0, %1, %2, %3;" : "=l"(d) : "l"(a), "l"(b), "l"(c));
    return d;
}
__device__ __forceinline__ float2 unpk(unsigned long long v) {
    float2 f;
    asm("mov.b64 {%0, %1}, %2;" : "=f"(f.x), "=f"(f.y) : "l"(v));
    return f;
}

// ---------------------------------------------------------------------------
__global__ void k_zero() {
    int i = blockIdx.x * 1024 + threadIdx.x;
    if (i < 2 * 128 * 128) g_S[i] = 0.f;
    if (i < 256) g_xsum[i] = 0.f;
}

// ---------------------------------------------------------------------------
// xp[b][c][n] = (1/16) * sum over 4x4 pixel patch
__global__ void __launch_bounds__(256) k_pool(const float* __restrict__ x) {
    int idx = blockIdx.x * 256 + threadIdx.x;          // 262144
    int n = idx & 1023;
    int c = (idx >> 10) & 127;
    int b = idx >> 17;
    int t = n >> 8, hy = (n >> 4) & 15, wx = n & 15;
    const float* p = x + (((b * 128 + c) * 4 + t) * 4096) + (hy * 4) * 64 + wx * 4;
    float s = 0.f;
#pragma unroll
    for (int r = 0; r < 4; ++r) {
        float4 v = *(const float4*)(p + r * 64);
        s += v.x + v.y + v.z + v.w;
    }
    g_xp[idx] = s * (1.f / 16.f);
}

// ---------------------------------------------------------------------------
// Gram S[b] += x x^T over 64-position chunks; also per-channel sums.
// grid = 2 x 256 = 512 CTAs, 256 threads (16x16), 8x8 tile via f32x2.
// smem layout xs[ss][c] (c contiguous, pad 132) -> conflict-light LDS.128.
__global__ void __launch_bounds__(256) k_gram(const float* __restrict__ x) {
    __shared__ __align__(16) float xs[64][132];
    int b = blockIdx.x >> 8;
    int s0 = (blockIdx.x & 255) * 64;
    int tid = threadIdx.x;
    int ty = tid >> 4, tx = tid & 15;

    // load+transpose: thread reads float4 along s, scatters to 4 rows; stores
    // have c fast-varying across the warp -> conflict-free.
    for (int i = tid; i < 2048; i += 256) {
        int c = i & 127, ss4 = i >> 7;                 // ss4 0..15
        float4 v = *(const float4*)(x + (size_t)(b * 128 + c) * 16384 + s0 + ss4 * 4);
        xs[ss4 * 4 + 0][c] = v.x;
        xs[ss4 * 4 + 1][c] = v.y;
        xs[ss4 * 4 + 2][c] = v.z;
        xs[ss4 * 4 + 3][c] = v.w;
    }
    __syncthreads();

    // per-channel partial sums (for GN mean); 2 threads per channel
    {
        int c = tid & 127, h = tid >> 7;
        float s = 0.f;
        for (int ss = h * 32; ss < h * 32 + 32; ++ss) s += xs[ss][c];
        atomicAdd(&g_xsum[b * 128 + c], s);
    }

    unsigned long long acc2[8][4];
#pragma unroll
    for (int u = 0; u < 8; ++u)
#pragma unroll
        for (int v = 0; v < 4; ++v) acc2[u][v] = 0ULL;

    for (int ss = 0; ss < 64; ++ss) {
        const float* ar = &xs[ss][ty * 8];
        float4 a0 = *(const float4*)ar;
        float4 a1 = *(const float4*)(ar + 4);
        const ulonglong2* bp = (const ulonglong2*)&xs[ss][tx * 8];
        ulonglong2 b0 = bp[0], b1 = bp[1];
        unsigned long long av[8] = {dup2(a0.x), dup2(a0.y), dup2(a0.z), dup2(a0.w),
                                    dup2(a1.x), dup2(a1.y), dup2(a1.z), dup2(a1.w)};
        unsigned long long bv[4] = {b0.x, b0.y, b1.x, b1.y};
#pragma unroll
        for (int u = 0; u < 8; ++u)
#pragma unroll
            for (int v = 0; v < 4; ++v) acc2[u][v] = fma2(av[u], bv[v], acc2[u][v]);
    }
#pragma unroll
    for (int u = 0; u < 8; ++u)
#pragma unroll
        for (int v = 0; v < 4; ++v) {
            float2 f = unpk(acc2[u][v]);
            float* dst = &g_S[(b * 128 + ty * 8 + u) * 128 + tx * 8 + v * 2];
            atomicAdd(dst, f.x);
            atomicAdd(dst + 1, f.y);
        }
}

// ---------------------------------------------------------------------------
// GN constants per (proj, b, group). Q gets attention scale 0.5 folded in.
__global__ void __launch_bounds__(128) k_gnconst(
    const float* __restrict__ Wq, const float* __restrict__ Wk, const float* __restrict__ Wv,
    const float* __restrict__ gqg, const float* __restrict__ gqb,
    const float* __restrict__ gkg, const float* __restrict__ gkb,
    const float* __restrict__ gvg, const float* __restrict__ gvb) {
    int pidx = blockIdx.x >> 6;           // 0=q 1=k 2=v
    int b = (blockIdx.x >> 5) & 1;
    int g = blockIdx.x & 31;
    const float* W   = pidx == 0 ? Wq  : (pidx == 1 ? Wk  : Wv);
    const float* gam = pidx == 0 ? gqg : (pidx == 1 ? gkg : gvg);
    const float* bet = pidx == 0 ? gqb : (pidx == 1 ? gkb : gvb);

    int i = threadIdx.x;
    float xb = g_xsum[b * 128 + i] * (1.f / 16384.f);
    float musum = 0.f;
    float accd[4] = {0.f, 0.f, 0.f, 0.f};
#pragma unroll
    for (int dd = 0; dd < 4; ++dd) musum += W[(g * 4 + dd) * 128 + i] * xb;

    const float* srow = g_S + (b * 128 + i) * 128;
    for (int j = 0; j < 128; ++j) {
        float sv = srow[j];
#pragma unroll
        for (int dd = 0; dd < 4; ++dd) accd[dd] = fmaf(sv, W[(g * 4 + dd) * 128 + j], accd[dd]);
    }
    float qsum = 0.f;
#pragma unroll
    for (int dd = 0; dd < 4; ++dd) qsum += W[(g * 4 + dd) * 128 + i] * accd[dd];

    __shared__ float r1[128], r2[128];
    __shared__ float s_mu, s_rs;
    r1[i] = musum; r2[i] = qsum;
    __syncthreads();
    for (int off = 64; off; off >>= 1) {
        if (i < off) { r1[i] += r1[i + off]; r2[i] += r2[i + off]; }
        __syncthreads();
    }
    if (i == 0) {
        float mu  = r1[0] * 0.25f;
        float ez2 = r2[0] * (1.f / (4.f * 16384.f));
        float var = ez2 - mu * mu;
        s_mu = mu;
        s_rs = rsqrtf(var + 1e-5f);
    }
    __syncthreads();
    if (i < 4) {
        int o = g * 4 + i;
        float sc = s_rs * gam[o];
        float bi = bet[o] - s_mu * sc;
        if (pidx == 0) { sc *= 0.5f; bi *= 0.5f; }     // fold 1/sqrt(d)
        g_gnsc[(pidx * 2 + b) * 128 + o] = sc;
        g_gnbi[(pidx * 2 + b) * 128 + o] = bi;
    }
}

// ---------------------------------------------------------------------------
// Pooled Q/K projection + GN affine.  grid = 2 x 32, 256 threads.
__global__ void __launch_bounds__(256) k_qkproj(const float* __restrict__ Wq,
                                                const float* __restrict__ Wk) {
    __shared__ __align__(16) float xs[128][32];
    int b = blockIdx.x >> 5;
    int n0 = (blockIdx.x & 31) * 32;
    int tid = threadIdx.x;
    for (int i = tid; i < 4096; i += 256) {
        int c = i >> 5, j = i & 31;
        xs[c][j] = g_xp[(b * 128 + c) * 1024 + n0 + j];
    }
    __syncthreads();

    int p = tid >> 7;
    int o = tid & 127;
    const float* Wrow = (p == 0 ? Wq : Wk) + o * 128;
    float4 acc[8];
#pragma unroll
    for (int i = 0; i < 8; ++i) acc[i] = make_float4(0.f, 0.f, 0.f, 0.f);

    for (int c = 0; c < 128; c += 4) {
        float4 w4 = *(const float4*)(Wrow + c);
        float wv[4] = {w4.x, w4.y, w4.z, w4.w};
#pragma unroll
        for (int s = 0; s < 4; ++s) {
            float w = wv[s];
            const float4* xr = (const float4*)&xs[c + s][0];
#pragma unroll
            for (int n4 = 0; n4 < 8; ++n4) {
                float4 xv = xr[n4];
                acc[n4].x = fmaf(w, xv.x, acc[n4].x);
                acc[n4].y = fmaf(w, xv.y, acc[n4].y);
                acc[n4].z = fmaf(w, xv.z, acc[n4].z);
                acc[n4].w = fmaf(w, xv.w, acc[n4].w);
            }
        }
    }
    float sc = g_gnsc[(p * 2 + b) * 128 + o];
    float bo = g_gnbi[(p * 2 + b) * 128 + o];
    int g = o >> 2, dd = o & 3;
    float* dst = (p == 0 ? g_Qn : g_Kn) + ((b * 32 + g) * 1024 + n0) * 4 + dd;
    float a[32];
#pragma unroll
    for (int n4 = 0; n4 < 8; ++n4) {
        a[n4 * 4 + 0] = acc[n4].x; a[n4 * 4 + 1] = acc[n4].y;
        a[n4 * 4 + 2] = acc[n4].z; a[n4 * 4 + 3] = acc[n4].w;
    }
#pragma unroll
    for (int nn = 0; nn < 32; ++nn) dst[nn * 4] = fmaf(a[nn], sc, bo);
}

// ---------------------------------------------------------------------------
// Full-res V projection + GN affine + layout  Vn[bg][m][dd*16+p]
__global__ void __launch_bounds__(256) k_vproj(const float* __restrict__ x,
                                               const float* __restrict__ Wv) {
    __shared__ __align__(16) float xs[32][256];
    __shared__ float ws[32][33];
    int bi = blockIdx.x;
    int b = bi >> 6;
    int t = (bi >> 4) & 3;
    int yb = bi & 15;
    int tid = threadIdx.x;
    int pos0 = (tid & 63) << 2;
    int ocb = tid >> 6;

    float acc[4][4][8];
#pragma unroll
    for (int a = 0; a < 4; ++a)
#pragma unroll
        for (int i = 0; i < 4; ++i)
#pragma unroll
            for (int j = 0; j < 8; ++j) acc[a][i][j] = 0.f;

    const float* xbase = x + ((b * 128) * 4 + t) * 4096 + (yb * 4) * 64;

    for (int ck = 0; ck < 4; ++ck) {
        __syncthreads();
        for (int i = tid; i < 32 * 256; i += 256) {
            int cl = i >> 8, posl = i & 255;
            xs[cl][posl] = xbase[(ck * 32 + cl) * 16384 + posl];
        }
#pragma unroll
        for (int og = 0; og < 4; ++og) {
            __syncthreads();
            for (int i = tid; i < 1024; i += 256) {
                int ocl = i >> 5, cc = i & 31;
                ws[ocl][cc] = Wv[(og * 32 + ocl) * 128 + ck * 32 + cc];
            }
            __syncthreads();
            for (int cc = 0; cc < 32; ++cc) {
                float4 a4 = *(const float4*)&xs[cc][pos0];
#pragma unroll
                for (int j = 0; j < 8; ++j) {
                    float w = ws[ocb * 8 + j][cc];
                    acc[og][0][j] = fmaf(a4.x, w, acc[og][0][j]);
                    acc[og][1][j] = fmaf(a4.y, w, acc[og][1][j]);
                    acc[og][2][j] = fmaf(a4.z, w, acc[og][2][j]);
                    acc[og][3][j] = fmaf(a4.w, w, acc[og][3][j]);
                }
            }
        }
    }

#pragma unroll
    for (int og = 0; og < 4; ++og) {
#pragma unroll
        for (int j = 0; j < 8; ++j) {
            int o = og * 32 + ocb * 8 + j;
            float sc = g_gnsc[(2 * 2 + b) * 128 + o];
            float bo = g_gnbi[(2 * 2 + b) * 128 + o];
            int g = o >> 2, dd = o & 3;
            float* vb = g_Vn + ((b * 32 + g) * 1024) * 64 + dd * 16;
#pragma unroll
            for (int i = 0; i < 4; ++i) {
                int pos = pos0 + i;
                int r = pos >> 6, xx = pos & 63;
                int n = (t * 16 + yb) * 16 + (xx >> 2);
                int p = r * 4 + (xx & 3);
                vb[n * 64 + p] = fmaf(acc[og][i][j], sc, bo);
            }
        }
    }
}

// ---------------------------------------------------------------------------
// Fused attention.  grid = 512 CTAs, 128 threads. Thread = one query row.
// AV accumulation in packed f32x2 (FFMA2): 32 FFMA2 + 16 LDS.128 per key.
__global__ void __launch_bounds__(128) k_attn(const float* __restrict__ tab,
                                              const int* __restrict__ ridx,
                                              float* __restrict__ out) {
    __shared__ float sTab[6727];
    __shared__ float4 sK[64];
    __shared__ __align__(16) float sV[64 * 64];
    int bid = blockIdx.x;
    int nt = bid & 7, g = (bid >> 3) & 31, b = bid >> 8;
    int bg = b * 32 + g;
    int tid = threadIdx.x;

    for (int i = tid; i < 6727; i += 128) sTab[i] = tab[g * 6727 + i];

    int n = nt * 128 + tid;
    float4 q = ((const float4*)g_Qn)[bg * 1024 + n];   // scale pre-folded
    float qx = q.x, qy = q.y, qz = q.z, qw = q.w;

    unsigned long long acc2[32];
#pragma unroll
    for (int i = 0; i < 32; ++i) acc2[i] = 0ULL;
    float l = 0.f;

    const int4* idxp = (const int4*)(ridx + (size_t)n * 1024);

    for (int m0 = 0; m0 < 1024; m0 += 64) {
        __syncthreads();
        if (tid < 64) sK[tid] = ((const float4*)g_Kn)[bg * 1024 + m0 + tid];
        const float4* vsrc = ((const float4*)g_Vn) + ((size_t)bg * 1024 + m0) * 16;
        for (int i = tid; i < 1024; i += 128) ((float4*)sV)[i] = vsrc[i];
        __syncthreads();

#pragma unroll 1
        for (int mq = 0; mq < 16; ++mq) {
            int4 iv = idxp[(m0 >> 2) + mq];
            int ids[4] = {iv.x, iv.y, iv.z, iv.w};
#pragma unroll
            for (int u = 0; u < 4; ++u) {
                int mm = mq * 4 + u;
                float4 kk = sK[mm];
                float s = sTab[ids[u]];
                s = fmaf(qx, kk.x, s);
                s = fmaf(qy, kk.y, s);
                s = fmaf(qz, kk.z, s);
                s = fmaf(qw, kk.w, s);
                float e = __expf(s);
                l += e;
                unsigned long long e2 = dup2(e);
                const ulonglong2* vr = (const ulonglong2*)(sV + mm * 64);
#pragma unroll
                for (int j = 0; j < 16; ++j) {
                    ulonglong2 vv = vr[j];
                    acc2[2 * j]     = fma2(e2, vv.x, acc2[2 * j]);
                    acc2[2 * j + 1] = fma2(e2, vv.y, acc2[2 * j + 1]);
                }
            }
        }
    }

    float inv = 1.0f / l;
    float accf[64];
#pragma unroll
    for (int i = 0; i < 32; ++i) {
        float2 f = unpk(acc2[i]);
        accf[2 * i] = f.x; accf[2 * i + 1] = f.y;
    }
    int t = n >> 8, hy = (n >> 4) & 15, wx = n & 15;
#pragma unroll
    for (int dd = 0; dd < 4; ++dd) {
        float* ob = out + (((b * 128 + g * 4 + dd) * 4 + t) * 4096);
#pragma unroll
        for (int pp = 0; pp < 16; ++pp) {
            int y = hy * 4 + (pp >> 2);
            int xx = wx * 4 + (pp & 3);
            ob[y * 64 + xx] = accf[dd * 16 + pp] * inv;
        }
    }
}

// ---------------------------------------------------------------------------
extern "C" void kernel_launch(void* const* d_in, const int* in_sizes, int n_in,
                              void* d_out, int out_size) {
    const float* x   = (const float*)d_in[0];
    const float* Wq  = (const float*)d_in[1];
    const float* Wk  = (const float*)d_in[2];
    const float* Wv  = (const float*)d_in[3];
    const float* gqg = (const float*)d_in[4];
    const float* gqb = (const float*)d_in[5];
    const float* gkg = (const float*)d_in[6];
    const float* gkb = (const float*)d_in[7];
    const float* gvg = (const float*)d_in[8];
    const float* gvb = (const float*)d_in[9];
    const float* tab = (const float*)d_in[10];
    const int*   ri  = (const int*)d_in[11];
    float* out = (float*)d_out;

    k_zero<<<32, 1024>>>();
    k_pool<<<1024, 256>>>(x);
    k_gram<<<512, 256>>>(x);
    k_gnconst<<<192, 128>>>(Wq, Wk, Wv, gqg, gqb, gkg, gkb, gvg, gvb);
    k_qkproj<<<64, 256>>>(Wq, Wk);
    k_vproj<<<128, 256>>>(x, Wv);
    k_attn<<<512, 128>>>(tab, ri, out);
}

// round 5
// speedup vs baseline: 1.5687x; 1.3444x over previous
#include <cuda_runtime.h>
#include <cuda_fp16.h>
#include <cstdint>

// ---------------------------------------------------------------------------
// PTAttention3D  (B=2, C=128, T=4, H=W=64, heads=32, d=4, patch 4x4)
// N = 1024 tokens, P = 16 pixels/patch, table = 7*31*31 = 6727
//
//   k_zero    : zero Gram + channel-sum accumulators
//   k_pool    : xp[b][c][n]  = patch means of x
//   k_gram    : S[b] = sum_s x x^T  AND  xsum[b][c] (f32x2 FMA)
//   k_gnconst : GN scale/bias per (proj,b,channel); Gram staged in smem
//   k_qkproj  : pooled Q,K projection + GN affine -> g_Qn, g_Kn [bg][n][4]
//   k_vproj   : full-res V projection + GN affine -> g_Vh fp16 [bg][dim][m]
//   k_attn    : 2-pass softmax + HMMA (mma.sync m16n8k16) P@V
// ---------------------------------------------------------------------------

__device__ float g_xp[2 * 128 * 1024];
__device__ float g_xsum[256];
__device__ float g_S[2 * 128 * 128];
__device__ float g_gnsc[3 * 2 * 128];
__device__ float g_gnbi[3 * 2 * 128];
__device__ float g_Qn[2 * 32 * 1024 * 4];
__device__ float g_Kn[2 * 32 * 1024 * 4];
__device__ __half g_Vh[2 * 32 * 64 * 1024];     // [bg][dim=dd*16+p][m]

// ---- packed f32x2 helpers --------------------------------------------------
__device__ __forceinline__ unsigned long long dup2(float x) {
    unsigned long long r; unsigned u = __float_as_uint(x);
    asm("mov.b64 %0, {%1, %1};" : "=l"(r) : "r"(u));
    return r;
}
__device__ __forceinline__ unsigned long long fma2(unsigned long long a,
                                                   unsigned long long b,
                                                   unsigned long long c) {
    unsigned long long d;
    asm("fma.rn.f32x2 %0, %1, %2, %3;" : "=l"(d) : "l"(a), "l"(b), "l"(c));
    return d;
}
__device__ __forceinline__ float2 unpk(unsigned long long v) {
    float2 f;
    asm("mov.b64 {%0, %1}, %2;" : "=f"(f.x), "=f"(f.y) : "l"(v));
    return f;
}

__device__ __forceinline__ uint32_t smem_u32(const void* p) {
    uint32_t a;
    asm("{ .reg .u64 t; cvta.to.shared.u64 t, %1; cvt.u32.u64 %0, t; }" : "=r"(a) : "l"(p));
    return a;
}

// ---------------------------------------------------------------------------
__global__ void k_zero() {
    int i = blockIdx.x * 1024 + threadIdx.x;
    if (i < 2 * 128 * 128) g_S[i] = 0.f;
    if (i < 256) g_xsum[i] = 0.f;
}

// ---------------------------------------------------------------------------
__global__ void __launch_bounds__(256) k_pool(const float* __restrict__ x) {
    int idx = blockIdx.x * 256 + threadIdx.x;
    int n = idx & 1023;
    int c = (idx >> 10) & 127;
    int b = idx >> 17;
    int t = n >> 8, hy = (n >> 4) & 15, wx = n & 15;
    const float* p = x + (((b * 128 + c) * 4 + t) * 4096) + (hy * 4) * 64 + wx * 4;
    float s = 0.f;
#pragma unroll
    for (int r = 0; r < 4; ++r) {
        float4 v = *(const float4*)(p + r * 64);
        s += v.x + v.y + v.z + v.w;
    }
    g_xp[idx] = s * (1.f / 16.f);
}

// ---------------------------------------------------------------------------
__global__ void __launch_bounds__(256) k_gram(const float* __restrict__ x) {
    __shared__ __align__(16) float xs[64][132];
    int b = blockIdx.x >> 8;
    int s0 = (blockIdx.x & 255) * 64;
    int tid = threadIdx.x;
    int ty = tid >> 4, tx = tid & 15;

    for (int i = tid; i < 2048; i += 256) {
        int c = i & 127, ss4 = i >> 7;
        float4 v = *(const float4*)(x + (size_t)(b * 128 + c) * 16384 + s0 + ss4 * 4);
        xs[ss4 * 4 + 0][c] = v.x;
        xs[ss4 * 4 + 1][c] = v.y;
        xs[ss4 * 4 + 2][c] = v.z;
        xs[ss4 * 4 + 3][c] = v.w;
    }
    __syncthreads();

    {
        int c = tid & 127, h = tid >> 7;
        float s = 0.f;
        for (int ss = h * 32; ss < h * 32 + 32; ++ss) s += xs[ss][c];
        atomicAdd(&g_xsum[b * 128 + c], s);
    }

    unsigned long long acc2[8][4];
#pragma unroll
    for (int u = 0; u < 8; ++u)
#pragma unroll
        for (int v = 0; v < 4; ++v) acc2[u][v] = 0ULL;

    for (int ss = 0; ss < 64; ++ss) {
        const float* ar = &xs[ss][ty * 8];
        float4 a0 = *(const float4*)ar;
        float4 a1 = *(const float4*)(ar + 4);
        const ulonglong2* bp = (const ulonglong2*)&xs[ss][tx * 8];
        ulonglong2 b0 = bp[0], b1 = bp[1];
        unsigned long long av[8] = {dup2(a0.x), dup2(a0.y), dup2(a0.z), dup2(a0.w),
                                    dup2(a1.x), dup2(a1.y), dup2(a1.z), dup2(a1.w)};
        unsigned long long bv[4] = {b0.x, b0.y, b1.x, b1.y};
#pragma unroll
        for (int u = 0; u < 8; ++u)
#pragma unroll
            for (int v = 0; v < 4; ++v) acc2[u][v] = fma2(av[u], bv[v], acc2[u][v]);
    }
#pragma unroll
    for (int u = 0; u < 8; ++u)
#pragma unroll
        for (int v = 0; v < 4; ++v) {
            float2 f = unpk(acc2[u][v]);
            float* dst = &g_S[(b * 128 + ty * 8 + u) * 128 + tx * 8 + v * 2];
            atomicAdd(dst, f.x);
            atomicAdd(dst + 1, f.y);
        }
}

// ---------------------------------------------------------------------------
// GN constants; Gram matrix staged in dynamic smem (stride 133, conflict-free).
__global__ void __launch_bounds__(128) k_gnconst(
    const float* __restrict__ Wq, const float* __restrict__ Wk, const float* __restrict__ Wv,
    const float* __restrict__ gqg, const float* __restrict__ gqb,
    const float* __restrict__ gkg, const float* __restrict__ gkb,
    const float* __restrict__ gvg, const float* __restrict__ gvb) {
    extern __shared__ float sS[];                      // 128*133 floats
    int pidx = blockIdx.x >> 6;
    int b = (blockIdx.x >> 5) & 1;
    int g = blockIdx.x & 31;
    const float* W   = pidx == 0 ? Wq  : (pidx == 1 ? Wk  : Wv);
    const float* gam = pidx == 0 ? gqg : (pidx == 1 ? gkg : gvg);
    const float* bet = pidx == 0 ? gqb : (pidx == 1 ? gkb : gvb);

    int i = threadIdx.x;
    for (int idx = i; idx < 4096; idx += 128) {
        float4 v = ((const float4*)(g_S + b * 16384))[idx];
        int r = idx >> 5, c4 = (idx & 31) * 4;
        float* dst = sS + r * 133 + c4;
        dst[0] = v.x; dst[1] = v.y; dst[2] = v.z; dst[3] = v.w;
    }
    __syncthreads();

    float xb = g_xsum[b * 128 + i] * (1.f / 16384.f);
    float musum = 0.f;
    float accd[4] = {0.f, 0.f, 0.f, 0.f};
#pragma unroll
    for (int dd = 0; dd < 4; ++dd) musum += W[(g * 4 + dd) * 128 + i] * xb;

    const float* srow = sS + i * 133;
#pragma unroll 4
    for (int j = 0; j < 128; ++j) {
        float sv = srow[j];
#pragma unroll
        for (int dd = 0; dd < 4; ++dd) accd[dd] = fmaf(sv, W[(g * 4 + dd) * 128 + j], accd[dd]);
    }
    float qsum = 0.f;
#pragma unroll
    for (int dd = 0; dd < 4; ++dd) qsum += W[(g * 4 + dd) * 128 + i] * accd[dd];

    __shared__ float r1[128], r2[128];
    __shared__ float s_mu, s_rs;
    r1[i] = musum; r2[i] = qsum;
    __syncthreads();
    for (int off = 64; off; off >>= 1) {
        if (i < off) { r1[i] += r1[i + off]; r2[i] += r2[i + off]; }
        __syncthreads();
    }
    if (i == 0) {
        float mu  = r1[0] * 0.25f;
        float ez2 = r2[0] * (1.f / (4.f * 16384.f));
        float var = ez2 - mu * mu;
        s_mu = mu;
        s_rs = rsqrtf(var + 1e-5f);
    }
    __syncthreads();
    if (i < 4) {
        int o = g * 4 + i;
        float sc = s_rs * gam[o];
        float bi = bet[o] - s_mu * sc;
        if (pidx == 0) { sc *= 0.5f; bi *= 0.5f; }     // fold 1/sqrt(d)
        g_gnsc[(pidx * 2 + b) * 128 + o] = sc;
        g_gnbi[(pidx * 2 + b) * 128 + o] = bi;
    }
}

// ---------------------------------------------------------------------------
__global__ void __launch_bounds__(256) k_qkproj(const float* __restrict__ Wq,
                                                const float* __restrict__ Wk) {
    __shared__ __align__(16) float xs[128][32];
    int b = blockIdx.x >> 5;
    int n0 = (blockIdx.x & 31) * 32;
    int tid = threadIdx.x;
    for (int i = tid; i < 4096; i += 256) {
        int c = i >> 5, j = i & 31;
        xs[c][j] = g_xp[(b * 128 + c) * 1024 + n0 + j];
    }
    __syncthreads();

    int p = tid >> 7;
    int o = tid & 127;
    const float* Wrow = (p == 0 ? Wq : Wk) + o * 128;
    float4 acc[8];
#pragma unroll
    for (int i = 0; i < 8; ++i) acc[i] = make_float4(0.f, 0.f, 0.f, 0.f);

    for (int c = 0; c < 128; c += 4) {
        float4 w4 = *(const float4*)(Wrow + c);
        float wv[4] = {w4.x, w4.y, w4.z, w4.w};
#pragma unroll
        for (int s = 0; s < 4; ++s) {
            float w = wv[s];
            const float4* xr = (const float4*)&xs[c + s][0];
#pragma unroll
            for (int n4 = 0; n4 < 8; ++n4) {
                float4 xv = xr[n4];
                acc[n4].x = fmaf(w, xv.x, acc[n4].x);
                acc[n4].y = fmaf(w, xv.y, acc[n4].y);
                acc[n4].z = fmaf(w, xv.z, acc[n4].z);
                acc[n4].w = fmaf(w, xv.w, acc[n4].w);
            }
        }
    }
    float sc = g_gnsc[(p * 2 + b) * 128 + o];
    float bo = g_gnbi[(p * 2 + b) * 128 + o];
    int g = o >> 2, dd = o & 3;
    float* dst = (p == 0 ? g_Qn : g_Kn) + ((b * 32 + g) * 1024 + n0) * 4 + dd;
    float a[32];
#pragma unroll
    for (int n4 = 0; n4 < 8; ++n4) {
        a[n4 * 4 + 0] = acc[n4].x; a[n4 * 4 + 1] = acc[n4].y;
        a[n4 * 4 + 2] = acc[n4].z; a[n4 * 4 + 3] = acc[n4].w;
    }
#pragma unroll
    for (int nn = 0; nn < 32; ++nn) dst[nn * 4] = fmaf(a[nn], sc, bo);
}

// ---------------------------------------------------------------------------
// V projection + GN affine -> fp16, layout [bg][dim=dd*16+p][m]
__global__ void __launch_bounds__(256) k_vproj(const float* __restrict__ x,
                                               const float* __restrict__ Wv) {
    __shared__ __align__(16) float xs[32][256];
    __shared__ float ws[32][33];
    int bi = blockIdx.x;
    int b = bi >> 6;
    int t = (bi >> 4) & 3;
    int yb = bi & 15;
    int tid = threadIdx.x;
    int pos0 = (tid & 63) << 2;
    int ocb = tid >> 6;

    float acc[4][4][8];
#pragma unroll
    for (int a = 0; a < 4; ++a)
#pragma unroll
        for (int i = 0; i < 4; ++i)
#pragma unroll
            for (int j = 0; j < 8; ++j) acc[a][i][j] = 0.f;

    const float* xbase = x + ((b * 128) * 4 + t) * 4096 + (yb * 4) * 64;

    for (int ck = 0; ck < 4; ++ck) {
        __syncthreads();
        for (int i = tid; i < 32 * 256; i += 256) {
            int cl = i >> 8, posl = i & 255;
            xs[cl][posl] = xbase[(ck * 32 + cl) * 16384 + posl];
        }
#pragma unroll
        for (int og = 0; og < 4; ++og) {
            __syncthreads();
            for (int i = tid; i < 1024; i += 256) {
                int ocl = i >> 5, cc = i & 31;
                ws[ocl][cc] = Wv[(og * 32 + ocl) * 128 + ck * 32 + cc];
            }
            __syncthreads();
            for (int cc = 0; cc < 32; ++cc) {
                float4 a4 = *(const float4*)&xs[cc][pos0];
#pragma unroll
                for (int j = 0; j < 8; ++j) {
                    float w = ws[ocb * 8 + j][cc];
                    acc[og][0][j] = fmaf(a4.x, w, acc[og][0][j]);
                    acc[og][1][j] = fmaf(a4.y, w, acc[og][1][j]);
                    acc[og][2][j] = fmaf(a4.z, w, acc[og][2][j]);
                    acc[og][3][j] = fmaf(a4.w, w, acc[og][3][j]);
                }
            }
        }
    }

#pragma unroll
    for (int og = 0; og < 4; ++og) {
#pragma unroll
        for (int j = 0; j < 8; ++j) {
            int o = og * 32 + ocb * 8 + j;
            float sc = g_gnsc[(2 * 2 + b) * 128 + o];
            float bo = g_gnbi[(2 * 2 + b) * 128 + o];
            int g = o >> 2, dd = o & 3;
            int bg = b * 32 + g;
#pragma unroll
            for (int i = 0; i < 4; ++i) {
                int pos = pos0 + i;
                int r = pos >> 6, xx = pos & 63;
                int n = (t * 16 + yb) * 16 + (xx >> 2);
                int p = r * 4 + (xx & 3);
                float val = fmaf(acc[og][i][j], sc, bo);
                g_Vh[((size_t)(bg * 64 + dd * 16 + p)) * 1024 + n] = __float2half(val);
            }
        }
    }
}

// ---------------------------------------------------------------------------
// Fused attention with HMMA.  grid = 512 CTAs, 128 threads (4 warps).
// Thread = 1 query for softmax; warp = 32 query rows for the P@V MMA.
// A = P [128q x 64k] fp16 (row-major), B = Vt [64d x 64k] fp16 (n-major ==
// col-major B for mma .row.col), C = [128q x 64d] fp32 fragments.
//
// dyn smem (bytes):
//   0      : table (26908, pad 26912)
//   26912  : K (float4 x 1024 = 16384)
//   43296  : L (128 floats, 512)
//   43808  : P  tile, 128 rows x 72 halves (18432)
//   62240  : Vt tile,  64 rows x 72 halves (9216)   total 71456
__global__ void __launch_bounds__(128) k_attn(const float* __restrict__ tab,
                                              const int* __restrict__ ridx,
                                              float* __restrict__ out) {
    extern __shared__ __align__(16) char sm[];
    float* sTab = (float*)sm;
    float4* sK  = (float4*)(sm + 26912);
    float* sL   = (float*)(sm + 43296);
    __half* sP  = (__half*)(sm + 43808);
    __half* sVt = (__half*)(sm + 62240);

    int bid = blockIdx.x;
    int nt = bid & 7, g = (bid >> 3) & 31, b = bid >> 8;
    int bg = b * 32 + g;
    int tid = threadIdx.x;
    int lane = tid & 31, wid = tid >> 5;

    for (int i = tid; i < 6727; i += 128) sTab[i] = tab[g * 6727 + i];
    for (int i = tid; i < 1024; i += 128) sK[i] = ((const float4*)g_Kn)[bg * 1024 + i];
    __syncthreads();

    int n = nt * 128 + tid;
    float4 q = ((const float4*)g_Qn)[bg * 1024 + n];   // 1/sqrt(d) pre-folded
    const int4* idxp = (const int4*)(ridx + (size_t)n * 1024);

    // ---- pass 1: row max ----
    float mx0 = -1e30f, mx1 = -1e30f, mx2 = -1e30f, mx3 = -1e30f;
#pragma unroll 4
    for (int m4 = 0; m4 < 256; ++m4) {
        int4 iv = idxp[m4];
        float4 k0 = sK[m4 * 4 + 0], k1 = sK[m4 * 4 + 1];
        float4 k2 = sK[m4 * 4 + 2], k3 = sK[m4 * 4 + 3];
        float s0 = sTab[iv.x], s1 = sTab[iv.y], s2 = sTab[iv.z], s3 = sTab[iv.w];
        s0 = fmaf(q.x, k0.x, s0); s0 = fmaf(q.y, k0.y, s0); s0 = fmaf(q.z, k0.z, s0); s0 = fmaf(q.w, k0.w, s0);
        s1 = fmaf(q.x, k1.x, s1); s1 = fmaf(q.y, k1.y, s1); s1 = fmaf(q.z, k1.z, s1); s1 = fmaf(q.w, k1.w, s1);
        s2 = fmaf(q.x, k2.x, s2); s2 = fmaf(q.y, k2.y, s2); s2 = fmaf(q.z, k2.z, s2); s2 = fmaf(q.w, k2.w, s2);
        s3 = fmaf(q.x, k3.x, s3); s3 = fmaf(q.y, k3.y, s3); s3 = fmaf(q.z, k3.z, s3); s3 = fmaf(q.w, k3.w, s3);
        mx0 = fmaxf(mx0, s0); mx1 = fmaxf(mx1, s1); mx2 = fmaxf(mx2, s2); mx3 = fmaxf(mx3, s3);
    }
    float mx = fmaxf(fmaxf(mx0, mx1), fmaxf(mx2, mx3));

    // ---- pass 2: per-tile exp -> smem P, V -> smem, warp HMMA ----
    float acc[2][8][4];
#pragma unroll
    for (int mt = 0; mt < 2; ++mt)
#pragma unroll
        for (int nb = 0; nb < 8; ++nb)
#pragma unroll
            for (int cix = 0; cix < 4; ++cix) acc[mt][nb][cix] = 0.f;
    float l = 0.f;

    uint32_t sPb = smem_u32(sP);
    uint32_t sVb = smem_u32(sVt);
    int q0 = wid * 32;

    for (int ti = 0; ti < 16; ++ti) {
        int kb = ti * 64;

        // 64 e-values for this thread's query row
        unsigned hh[32];
#pragma unroll
        for (int mq = 0; mq < 16; ++mq) {
            int4 iv = idxp[(kb >> 2) + mq];
            float4 k0 = sK[kb + mq * 4 + 0], k1 = sK[kb + mq * 4 + 1];
            float4 k2 = sK[kb + mq * 4 + 2], k3 = sK[kb + mq * 4 + 3];
            float s0 = sTab[iv.x], s1 = sTab[iv.y], s2 = sTab[iv.z], s3 = sTab[iv.w];
            s0 = fmaf(q.x, k0.x, s0); s0 = fmaf(q.y, k0.y, s0); s0 = fmaf(q.z, k0.z, s0); s0 = fmaf(q.w, k0.w, s0);
            s1 = fmaf(q.x, k1.x, s1); s1 = fmaf(q.y, k1.y, s1); s1 = fmaf(q.z, k1.z, s1); s1 = fmaf(q.w, k1.w, s1);
            s2 = fmaf(q.x, k2.x, s2); s2 = fmaf(q.y, k2.y, s2); s2 = fmaf(q.z, k2.z, s2); s2 = fmaf(q.w, k2.w, s2);
            s3 = fmaf(q.x, k3.x, s3); s3 = fmaf(q.y, k3.y, s3); s3 = fmaf(q.z, k3.z, s3); s3 = fmaf(q.w, k3.w, s3);
            float e0 = __expf(s0 - mx), e1 = __expf(s1 - mx);
            float e2 = __expf(s2 - mx), e3 = __expf(s3 - mx);
            l += (e0 + e1) + (e2 + e3);
            __half2 h01 = __floats2half2_rn(e0, e1);
            __half2 h23 = __floats2half2_rn(e2, e3);
            hh[mq * 2 + 0] = *(unsigned*)&h01;
            hh[mq * 2 + 1] = *(unsigned*)&h23;
        }

        __syncthreads();   // previous tile's MMA reads done

        // store P row (query = tid): 16 x 8B stores
        {
            __half* pr = sP + tid * 72;
#pragma unroll
            for (int kk = 0; kk < 16; ++kk)
                *(uint2*)(pr + kk * 4) = make_uint2(hh[kk * 2], hh[kk * 2 + 1]);
        }
        // load Vt tile [64 dims x 64 keys]
#pragma unroll
        for (int r2 = 0; r2 < 4; ++r2) {
            int i = tid + r2 * 128;                    // 0..511
            int dim = i >> 3, seg = i & 7;
            uint4 v = *(const uint4*)(g_Vh + ((size_t)(bg * 64 + dim)) * 1024 + kb + seg * 8);
            *(uint4*)(sVt + dim * 72 + seg * 8) = v;
        }
        __syncthreads();

        // warp MMA: 4 k-steps x (2 M-tiles A-load, 8 N-tiles B-load + 2 mma)
        int arow = (lane & 7) + ((lane >> 3) & 1) * 8;
        int akoff = (lane >> 4) * 8;
        int brow = lane & 7;
        int bkoff = ((lane >> 3) & 1) * 8;
#pragma unroll
        for (int ks = 0; ks < 4; ++ks) {
            int k0 = ks * 16;
            unsigned af[2][4];
#pragma unroll
            for (int mt = 0; mt < 2; ++mt) {
                uint32_t aaddr = sPb + ((q0 + mt * 16 + arow) * 72 + k0 + akoff) * 2;
                asm volatile("ldmatrix.sync.aligned.m8n8.x4.shared.b16 {%0,%1,%2,%3}, [%4];"
                             : "=r"(af[mt][0]), "=r"(af[mt][1]), "=r"(af[mt][2]), "=r"(af[mt][3])
                             : "r"(aaddr));
            }
#pragma unroll
            for (int nb = 0; nb < 8; ++nb) {
                unsigned bf[2];
                uint32_t baddr = sVb + ((nb * 8 + brow) * 72 + k0 + bkoff) * 2;
                asm volatile("ldmatrix.sync.aligned.m8n8.x2.shared.b16 {%0,%1}, [%2];"
                             : "=r"(bf[0]), "=r"(bf[1]) : "r"(baddr));
#pragma unroll
                for (int mt = 0; mt < 2; ++mt) {
                    asm volatile(
                        "mma.sync.aligned.m16n8k16.row.col.f32.f16.f16.f32 "
                        "{%0,%1,%2,%3}, {%4,%5,%6,%7}, {%8,%9}, {%0,%1,%2,%3};"
                        : "+f"(acc[mt][nb][0]), "+f"(acc[mt][nb][1]),
                          "+f"(acc[mt][nb][2]), "+f"(acc[mt][nb][3])
                        : "r"(af[mt][0]), "r"(af[mt][1]), "r"(af[mt][2]), "r"(af[mt][3]),
                          "r"(bf[0]), "r"(bf[1]));
                }
            }
        }
    }

    sL[tid] = l;
    __syncthreads();

    // ---- epilogue: fragment scatter ----
#pragma unroll
    for (int mt = 0; mt < 2; ++mt) {
        int r0 = q0 + mt * 16 + (lane >> 2);
#pragma unroll
        for (int hf = 0; hf < 2; ++hf) {
            int qr = r0 + hf * 8;
            float inv = 1.0f / sL[qr];
            int n2 = nt * 128 + qr;
            int tt = n2 >> 8, hy = (n2 >> 4) & 15, wx = n2 & 15;
#pragma unroll
            for (int nb = 0; nb < 8; ++nb) {
                int col = nb * 8 + (lane & 3) * 2;
                int dd = col >> 4, pp = col & 15;
                int y = hy * 4 + (pp >> 2);
                int xx = wx * 4 + (pp & 3);
                float* ob = out + ((size_t)((b * 128 + g * 4 + dd) * 4 + tt)) * 4096 + y * 64 + xx;
                ob[0] = acc[mt][nb][hf * 2 + 0] * inv;
                ob[1] = acc[mt][nb][hf * 2 + 1] * inv;
            }
        }
    }
}

// ---------------------------------------------------------------------------
extern "C" void kernel_launch(void* const* d_in, const int* in_sizes, int n_in,
                              void* d_out, int out_size) {
    const float* x   = (const float*)d_in[0];
    const float* Wq  = (const float*)d_in[1];
    const float* Wk  = (const float*)d_in[2];
    const float* Wv  = (const float*)d_in[3];
    const float* gqg = (const float*)d_in[4];
    const float* gqb = (const float*)d_in[5];
    const float* gkg = (const float*)d_in[6];
    const float* gkb = (const float*)d_in[7];
    const float* gvg = (const float*)d_in[8];
    const float* gvb = (const float*)d_in[9];
    const float* tab = (const float*)d_in[10];
    const int*   ri  = (const int*)d_in[11];
    float* out = (float*)d_out;

    cudaFuncSetAttribute(k_gnconst, cudaFuncAttributeMaxDynamicSharedMemorySize, 128 * 133 * 4);
    cudaFuncSetAttribute(k_attn, cudaFuncAttributeMaxDynamicSharedMemorySize, 71456);

    k_zero<<<32, 1024>>>();
    k_pool<<<1024, 256>>>(x);
    k_gram<<<512, 256>>>(x);
    k_gnconst<<<192, 128, 128 * 133 * 4>>>(Wq, Wk, Wv, gqg, gqb, gkg, gkb, gvg, gvb);
    k_qkproj<<<64, 256>>>(Wq, Wk);
    k_vproj<<<128, 256>>>(x, Wv);
    k_attn<<<512, 128, 71456>>>(tab, ri, out);
}

// round 7
// speedup vs baseline: 2.1387x; 1.3634x over previous
#include <cuda_runtime.h>
#include <cuda_fp16.h>
#include <cstdint>

// ---------------------------------------------------------------------------
// PTAttention3D  (B=2, C=128, T=4, H=W=64, heads=32, d=4, patch 4x4)
// N = 1024 tokens, P = 16 pixels/patch, table = 7*31*31 = 6727
//
//   k_zero    : zero Gram + channel-sum accumulators
//   k_bias    : pregather bias table -> g_Bh fp16 [g][n][m]; per-g table max
//   k_pool    : xp[b][c][n]  = patch means of x
//   k_gram    : S[b] = sum_s x x^T  AND  xsum[b][c] (f32x2 FMA)
//   k_gnconst : GN scale/bias per (proj,b,channel); Gram staged in smem
//   k_qkproj  : pooled Q,K proj + GN affine -> g_Qn [bg][n][4], g_Kn [bg][4][n]
//   k_vproj   : full-res V projection + GN affine -> g_Vh fp16 [bg][dim][m]
//   k_attn    : bound-max softmax (fp16 exp) + HMMA P@V, l via ones-MMA
// ---------------------------------------------------------------------------

__device__ float g_xp[2 * 128 * 1024];
__device__ float g_xsum[256];
__device__ float g_S[2 * 128 * 128];
__device__ float g_gnsc[3 * 2 * 128];
__device__ float g_gnbi[3 * 2 * 128];
__device__ float g_Qn[2 * 32 * 1024 * 4];
__device__ float g_Kn[2 * 32 * 4 * 1024];       // [bg][d][n]  (SoA)
__device__ __half g_Vh[2 * 32 * 64 * 1024];     // [bg][dim=dd*16+p][m]
__device__ __half g_Bh[32 * 1024 * 1024];       // [g][n][m] pregathered bias
__device__ float g_tmax[32];

// ---- packed f32x2 helpers --------------------------------------------------
__device__ __forceinline__ unsigned long long dup2(float x) {
    unsigned long long r; unsigned u = __float_as_uint(x);
    asm("mov.b64 %0, {%1, %1};" : "=l"(r) : "r"(u));
    return r;
}
__device__ __forceinline__ unsigned long long fma2(unsigned long long a,
                                                   unsigned long long b,
                                                   unsigned long long c) {
    unsigned long long d;
    asm("fma.rn.f32x2 %0, %1, %2, %3;" : "=l"(d) : "l"(a), "l"(b), "l"(c));
    return d;
}
__device__ __forceinline__ float2 unpk(unsigned long long v) {
    float2 f;
    asm("mov.b64 {%0, %1}, %2;" : "=f"(f.x), "=f"(f.y) : "l"(v));
    return f;
}
__device__ __forceinline__ uint32_t smem_u32(const void* p) {
    uint32_t a;
    asm("{ .reg .u64 t; cvta.to.shared.u64 t, %1; cvt.u32.u64 %0, t; }" : "=r"(a) : "l"(p));
    return a;
}
__device__ __forceinline__ __half2 u2h(unsigned u) {
    __half2 h; *(unsigned*)&h = u; return h;
}
__device__ __forceinline__ unsigned h2u(__half2 h) { return *(unsigned*)&h; }

// ---------------------------------------------------------------------------
__global__ void k_zero() {
    int i = blockIdx.x * 1024 + threadIdx.x;
    if (i < 2 * 128 * 128) g_S[i] = 0.f;
    if (i < 256) g_xsum[i] = 0.f;
}

// ---------------------------------------------------------------------------
// Pregather bias: g_Bh[g][n][m] = tab[g][ridx[n][m]] in fp16; g_tmax[g].
// grid = 32 g x 16 query-chunks, 256 threads.
__global__ void __launch_bounds__(256) k_bias(const float* __restrict__ tab,
                                              const int* __restrict__ ridx) {
    __shared__ float sT[6727];
    __shared__ float red[256];
    int g = blockIdx.x >> 4;
    int ch = blockIdx.x & 15;
    int tid = threadIdx.x;
    float mxv = -1e30f;
    for (int i = tid; i < 6727; i += 256) {
        float v = tab[g * 6727 + i];
        sT[i] = v;
        mxv = fmaxf(mxv, v);
    }
    red[tid] = mxv;
    __syncthreads();
    for (int off = 128; off; off >>= 1) {
        if (tid < off) red[tid] = fmaxf(red[tid], red[tid + off]);
        __syncthreads();
    }
    if (ch == 0 && tid == 0) g_tmax[g] = red[0];

    for (int q = 0; q < 64; ++q) {
        int n = ch * 64 + q;
        int4 iv = ((const int4*)(ridx + (size_t)n * 1024))[tid];
        __half2 a = __floats2half2_rn(sT[iv.x], sT[iv.y]);
        __half2 b = __floats2half2_rn(sT[iv.z], sT[iv.w]);
        *(uint2*)(g_Bh + ((size_t)g << 20) + n * 1024 + tid * 4) =
            make_uint2(h2u(a), h2u(b));
    }
}

// ---------------------------------------------------------------------------
__global__ void __launch_bounds__(256) k_pool(const float* __restrict__ x) {
    int idx = blockIdx.x * 256 + threadIdx.x;
    int n = idx & 1023;
    int c = (idx >> 10) & 127;
    int b = idx >> 17;
    int t = n >> 8, hy = (n >> 4) & 15, wx = n & 15;
    const float* p = x + (((b * 128 + c) * 4 + t) * 4096) + (hy * 4) * 64 + wx * 4;
    float s = 0.f;
#pragma unroll
    for (int r = 0; r < 4; ++r) {
        float4 v = *(const float4*)(p + r * 64);
        s += v.x + v.y + v.z + v.w;
    }
    g_xp[idx] = s * (1.f / 16.f);
}

// ---------------------------------------------------------------------------
__global__ void __launch_bounds__(256) k_gram(const float* __restrict__ x) {
    __shared__ __align__(16) float xs[64][132];
    int b = blockIdx.x >> 8;
    int s0 = (blockIdx.x & 255) * 64;
    int tid = threadIdx.x;
    int ty = tid >> 4, tx = tid & 15;

    for (int i = tid; i < 2048; i += 256) {
        int c = i & 127, ss4 = i >> 7;
        float4 v = *(const float4*)(x + (size_t)(b * 128 + c) * 16384 + s0 + ss4 * 4);
        xs[ss4 * 4 + 0][c] = v.x;
        xs[ss4 * 4 + 1][c] = v.y;
        xs[ss4 * 4 + 2][c] = v.z;
        xs[ss4 * 4 + 3][c] = v.w;
    }
    __syncthreads();

    {
        int c = tid & 127, h = tid >> 7;
        float s = 0.f;
        for (int ss = h * 32; ss < h * 32 + 32; ++ss) s += xs[ss][c];
        atomicAdd(&g_xsum[b * 128 + c], s);
    }

    unsigned long long acc2[8][4];
#pragma unroll
    for (int u = 0; u < 8; ++u)
#pragma unroll
        for (int v = 0; v < 4; ++v) acc2[u][v] = 0ULL;

    for (int ss = 0; ss < 64; ++ss) {
        const float* ar = &xs[ss][ty * 8];
        float4 a0 = *(const float4*)ar;
        float4 a1 = *(const float4*)(ar + 4);
        const ulonglong2* bp = (const ulonglong2*)&xs[ss][tx * 8];
        ulonglong2 b0 = bp[0], b1 = bp[1];
        unsigned long long av[8] = {dup2(a0.x), dup2(a0.y), dup2(a0.z), dup2(a0.w),
                                    dup2(a1.x), dup2(a1.y), dup2(a1.z), dup2(a1.w)};
        unsigned long long bv[4] = {b0.x, b0.y, b1.x, b1.y};
#pragma unroll
        for (int u = 0; u < 8; ++u)
#pragma unroll
            for (int v = 0; v < 4; ++v) acc2[u][v] = fma2(av[u], bv[v], acc2[u][v]);
    }
#pragma unroll
    for (int u = 0; u < 8; ++u)
#pragma unroll
        for (int v = 0; v < 4; ++v) {
            float2 f = unpk(acc2[u][v]);
            float* dst = &g_S[(b * 128 + ty * 8 + u) * 128 + tx * 8 + v * 2];
            atomicAdd(dst, f.x);
            atomicAdd(dst + 1, f.y);
        }
}

// ---------------------------------------------------------------------------
__global__ void __launch_bounds__(128) k_gnconst(
    const float* __restrict__ Wq, const float* __restrict__ Wk, const float* __restrict__ Wv,
    const float* __restrict__ gqg, const float* __restrict__ gqb,
    const float* __restrict__ gkg, const float* __restrict__ gkb,
    const float* __restrict__ gvg, const float* __restrict__ gvb) {
    extern __shared__ float sS[];                      // 128*133 floats
    int pidx = blockIdx.x >> 6;
    int b = (blockIdx.x >> 5) & 1;
    int g = blockIdx.x & 31;
    const float* W   = pidx == 0 ? Wq  : (pidx == 1 ? Wk  : Wv);
    const float* gam = pidx == 0 ? gqg : (pidx == 1 ? gkg : gvg);
    const float* bet = pidx == 0 ? gqb : (pidx == 1 ? gkb : gvb);

    int i = threadIdx.x;
    for (int idx = i; idx < 4096; idx += 128) {
        float4 v = ((const float4*)(g_S + b * 16384))[idx];
        int r = idx >> 5, c4 = (idx & 31) * 4;
        float* dst = sS + r * 133 + c4;
        dst[0] = v.x; dst[1] = v.y; dst[2] = v.z; dst[3] = v.w;
    }
    __syncthreads();

    float xb = g_xsum[b * 128 + i] * (1.f / 16384.f);
    float musum = 0.f;
    float accd[4] = {0.f, 0.f, 0.f, 0.f};
#pragma unroll
    for (int dd = 0; dd < 4; ++dd) musum += W[(g * 4 + dd) * 128 + i] * xb;

    const float* srow = sS + i * 133;
#pragma unroll 4
    for (int j = 0; j < 128; ++j) {
        float sv = srow[j];
#pragma unroll
        for (int dd = 0; dd < 4; ++dd) accd[dd] = fmaf(sv, W[(g * 4 + dd) * 128 + j], accd[dd]);
    }
    float qsum = 0.f;
#pragma unroll
    for (int dd = 0; dd < 4; ++dd) qsum += W[(g * 4 + dd) * 128 + i] * accd[dd];

    __shared__ float r1[128], r2[128];
    __shared__ float s_mu, s_rs;
    r1[i] = musum; r2[i] = qsum;
    __syncthreads();
    for (int off = 64; off; off >>= 1) {
        if (i < off) { r1[i] += r1[i + off]; r2[i] += r2[i + off]; }
        __syncthreads();
    }
    if (i == 0) {
        float mu  = r1[0] * 0.25f;
        float ez2 = r2[0] * (1.f / (4.f * 16384.f));
        float var = ez2 - mu * mu;
        s_mu = mu;
        s_rs = rsqrtf(var + 1e-5f);
    }
    __syncthreads();
    if (i < 4) {
        int o = g * 4 + i;
        float sc = s_rs * gam[o];
        float bi = bet[o] - s_mu * sc;
        if (pidx == 0) { sc *= 0.5f; bi *= 0.5f; }     // fold 1/sqrt(d)
        g_gnsc[(pidx * 2 + b) * 128 + o] = sc;
        g_gnbi[(pidx * 2 + b) * 128 + o] = bi;
    }
}

// ---------------------------------------------------------------------------
__global__ void __launch_bounds__(256) k_qkproj(const float* __restrict__ Wq,
                                                const float* __restrict__ Wk) {
    __shared__ __align__(16) float xs[128][32];
    int b = blockIdx.x >> 5;
    int n0 = (blockIdx.x & 31) * 32;
    int tid = threadIdx.x;
    for (int i = tid; i < 4096; i += 256) {
        int c = i >> 5, j = i & 31;
        xs[c][j] = g_xp[(b * 128 + c) * 1024 + n0 + j];
    }
    __syncthreads();

    int p = tid >> 7;
    int o = tid & 127;
    const float* Wrow = (p == 0 ? Wq : Wk) + o * 128;
    float4 acc[8];
#pragma unroll
    for (int i = 0; i < 8; ++i) acc[i] = make_float4(0.f, 0.f, 0.f, 0.f);

    for (int c = 0; c < 128; c += 4) {
        float4 w4 = *(const float4*)(Wrow + c);
        float wv[4] = {w4.x, w4.y, w4.z, w4.w};
#pragma unroll
        for (int s = 0; s < 4; ++s) {
            float w = wv[s];
            const float4* xr = (const float4*)&xs[c + s][0];
#pragma unroll
            for (int n4 = 0; n4 < 8; ++n4) {
                float4 xv = xr[n4];
                acc[n4].x = fmaf(w, xv.x, acc[n4].x);
                acc[n4].y = fmaf(w, xv.y, acc[n4].y);
                acc[n4].z = fmaf(w, xv.z, acc[n4].z);
                acc[n4].w = fmaf(w, xv.w, acc[n4].w);
            }
        }
    }
    float sc = g_gnsc[(p * 2 + b) * 128 + o];
    float bo = g_gnbi[(p * 2 + b) * 128 + o];
    int g = o >> 2, dd = o & 3;
    float a[32];
#pragma unroll
    for (int n4 = 0; n4 < 8; ++n4) {
        a[n4 * 4 + 0] = acc[n4].x; a[n4 * 4 + 1] = acc[n4].y;
        a[n4 * 4 + 2] = acc[n4].z; a[n4 * 4 + 3] = acc[n4].w;
    }
    if (p == 0) {
        float* dst = g_Qn + ((b * 32 + g) * 1024 + n0) * 4 + dd;
#pragma unroll
        for (int nn = 0; nn < 32; ++nn) dst[nn * 4] = fmaf(a[nn], sc, bo);
    } else {
        float* dst = g_Kn + (b * 32 + g) * 4096 + dd * 1024 + n0;   // SoA [d][n]
#pragma unroll
        for (int nn = 0; nn < 32; ++nn) dst[nn] = fmaf(a[nn], sc, bo);
    }
}

// ---------------------------------------------------------------------------
// V projection + GN affine -> fp16, layout [bg][dim=dd*16+p][m]
__global__ void __launch_bounds__(256) k_vproj(const float* __restrict__ x,
                                               const float* __restrict__ Wv) {
    __shared__ __align__(16) float xs[32][256];
    __shared__ float ws[32][33];
    int bi = blockIdx.x;
    int b = bi >> 6;
    int t = (bi >> 4) & 3;
    int yb = bi & 15;
    int tid = threadIdx.x;
    int pos0 = (tid & 63) << 2;
    int ocb = tid >> 6;

    float acc[4][4][8];
#pragma unroll
    for (int a = 0; a < 4; ++a)
#pragma unroll
        for (int i = 0; i < 4; ++i)
#pragma unroll
            for (int j = 0; j < 8; ++j) acc[a][i][j] = 0.f;

    const float* xbase = x + ((b * 128) * 4 + t) * 4096 + (yb * 4) * 64;

    for (int ck = 0; ck < 4; ++ck) {
        __syncthreads();
        for (int i = tid; i < 32 * 256; i += 256) {
            int cl = i >> 8, posl = i & 255;
            xs[cl][posl] = xbase[(ck * 32 + cl) * 16384 + posl];
        }
#pragma unroll
        for (int og = 0; og < 4; ++og) {
            __syncthreads();
            for (int i = tid; i < 1024; i += 256) {
                int ocl = i >> 5, cc = i & 31;
                ws[ocl][cc] = Wv[(og * 32 + ocl) * 128 + ck * 32 + cc];
            }
            __syncthreads();
            for (int cc = 0; cc < 32; ++cc) {
                float4 a4 = *(const float4*)&xs[cc][pos0];
#pragma unroll
                for (int j = 0; j < 8; ++j) {
                    float w = ws[ocb * 8 + j][cc];
                    acc[og][0][j] = fmaf(a4.x, w, acc[og][0][j]);
                    acc[og][1][j] = fmaf(a4.y, w, acc[og][1][j]);
                    acc[og][2][j] = fmaf(a4.z, w, acc[og][2][j]);
                    acc[og][3][j] = fmaf(a4.w, w, acc[og][3][j]);
                }
            }
        }
    }

#pragma unroll
    for (int og = 0; og < 4; ++og) {
#pragma unroll
        for (int j = 0; j < 8; ++j) {
            int o = og * 32 + ocb * 8 + j;
            float sc = g_gnsc[(2 * 2 + b) * 128 + o];
            float bo = g_gnbi[(2 * 2 + b) * 128 + o];
            int g = o >> 2, dd = o & 3;
            int bg = b * 32 + g;
#pragma unroll
            for (int i = 0; i < 4; ++i) {
                int pos = pos0 + i;
                int r = pos >> 6, xx = pos & 63;
                int n = (t * 16 + yb) * 16 + (xx >> 2);
                int p = r * 4 + (xx & 3);
                float val = fmaf(acc[og][i][j], sc, bo);
                g_Vh[((size_t)(bg * 64 + dd * 16 + p)) * 1024 + n] = __float2half(val);
            }
        }
    }
}

// ---------------------------------------------------------------------------
// Fused attention.  grid = 512 CTAs, 128 threads (4 warps).
// Bound-max softmax: mx = max_m(q.k) + tabmax[g]  (no table gathers in pass 1).
// p = h2exp(cvt_f16(qk - mx) + bias_f16);  l from extra ones-column MMA.
//
// dyn smem (bytes):
//   0      : K SoA [4][1024] f32  (16384)
//   16384  : P  tile, 128 rows x 72 halves (18432)
//   34816  : Vt tile,  64 rows x 72 halves (9216)   total 44032
__global__ void __launch_bounds__(128) k_attn(float* __restrict__ out) {
    extern __shared__ __align__(16) char sm[];
    float* sKf = (float*)sm;
    __half* sP  = (__half*)(sm + 16384);
    __half* sVt = (__half*)(sm + 34816);

    int bid = blockIdx.x;
    int nt = bid & 7, g = (bid >> 3) & 31, b = bid >> 8;
    int bg = b * 32 + g;
    int tid = threadIdx.x;
    int lane = tid & 31, wid = tid >> 5;

    for (int i = tid; i < 4096; i += 128) sKf[i] = g_Kn[bg * 4096 + i];
    __syncthreads();

    int n = nt * 128 + tid;
    float4 q = ((const float4*)g_Qn)[bg * 1024 + n];   // 1/sqrt(d) pre-folded
    unsigned long long qx2 = dup2(q.x), qy2 = dup2(q.y);
    unsigned long long qz2 = dup2(q.z), qw2 = dup2(q.w);

    const ulonglong2* kx2 = (const ulonglong2*)sKf;
    const ulonglong2* ky2 = (const ulonglong2*)(sKf + 1024);
    const ulonglong2* kz2 = (const ulonglong2*)(sKf + 2048);
    const ulonglong2* kw2 = (const ulonglong2*)(sKf + 3072);

    // ---- pass 1: mx = max(q.k) + tabmax ----
    float mx = -1e30f;
    unsigned long long z2 = 0ULL;
#pragma unroll 4
    for (int m4 = 0; m4 < 256; ++m4) {
        ulonglong2 ka = kx2[m4], kbq = ky2[m4], kc = kz2[m4], kd = kw2[m4];
        unsigned long long sa = fma2(qx2, ka.x, fma2(qy2, kbq.x, fma2(qz2, kc.x, fma2(qw2, kd.x, z2))));
        unsigned long long sb = fma2(qx2, ka.y, fma2(qy2, kbq.y, fma2(qz2, kc.y, fma2(qw2, kd.y, z2))));
        float2 fa = unpk(sa), fb = unpk(sb);
        mx = fmaxf(mx, fmaxf(fmaxf(fa.x, fa.y), fmaxf(fb.x, fb.y)));
    }
    mx += g_tmax[g];
    unsigned long long nmx2 = dup2(-mx);

    // ---- pass 2: tiles ----
    float acc[2][8][4];
    float lfrag[2][4];
#pragma unroll
    for (int mt = 0; mt < 2; ++mt) {
#pragma unroll
        for (int nb = 0; nb < 8; ++nb)
#pragma unroll
            for (int cix = 0; cix < 4; ++cix) acc[mt][nb][cix] = 0.f;
#pragma unroll
        for (int cix = 0; cix < 4; ++cix) lfrag[mt][cix] = 0.f;
    }

    uint32_t sPb = smem_u32(sP);
    uint32_t sVb = smem_u32(sVt);
    int q0 = wid * 32;
    const uint4* biasrow = (const uint4*)(g_Bh + ((size_t)g << 20) + (size_t)n * 1024);
    const unsigned ONES = 0x3C003C00u;

    int vdim = tid >> 3, vseg = tid & 7;               // for V loads (i = tid + r2*128)

    for (int ti = 0; ti < 16; ++ti) {
        int kb = ti * 64;

        // prefetch V tile [64 dims x 64 keys]
        uint4 vv[4];
#pragma unroll
        for (int r2 = 0; r2 < 4; ++r2) {
            int dim = vdim + r2 * 16;
            vv[r2] = *(const uint4*)(g_Vh + ((size_t)(bg * 64 + dim)) * 1024 + kb + vseg * 8);
        }

        __syncthreads();   // previous tile's MMA reads done

#pragma unroll
        for (int r2 = 0; r2 < 4; ++r2) {
            int dim = vdim + r2 * 16;
            *(uint4*)(sVt + dim * 72 + vseg * 8) = vv[r2];
        }

        // softmax: 8 segs x 8 keys
#pragma unroll
        for (int seg = 0; seg < 8; ++seg) {
            uint4 bv = biasrow[ti * 8 + seg];
            int m4 = (kb >> 2) + seg * 2;
            ulonglong2 ka0 = kx2[m4],     ka1 = ky2[m4],     ka2 = kz2[m4],     ka3 = kw2[m4];
            ulonglong2 kb0 = kx2[m4 + 1], kb1 = ky2[m4 + 1], kb2 = kz2[m4 + 1], kb3 = kw2[m4 + 1];
            unsigned long long s0 = fma2(qx2, ka0.x, fma2(qy2, ka1.x, fma2(qz2, ka2.x, fma2(qw2, ka3.x, nmx2))));
            unsigned long long s1 = fma2(qx2, ka0.y, fma2(qy2, ka1.y, fma2(qz2, ka2.y, fma2(qw2, ka3.y, nmx2))));
            unsigned long long s2 = fma2(qx2, kb0.x, fma2(qy2, kb1.x, fma2(qz2, kb2.x, fma2(qw2, kb3.x, nmx2))));
            unsigned long long s3 = fma2(qx2, kb0.y, fma2(qy2, kb1.y, fma2(qz2, kb2.y, fma2(qw2, kb3.y, nmx2))));
            float2 f0 = unpk(s0), f1 = unpk(s1), f2 = unpk(s2), f3 = unpk(s3);
            __half2 h0 = h2exp(__hadd2(__floats2half2_rn(f0.x, f0.y), u2h(bv.x)));
            __half2 h1 = h2exp(__hadd2(__floats2half2_rn(f1.x, f1.y), u2h(bv.y)));
            __half2 h2 = h2exp(__hadd2(__floats2half2_rn(f2.x, f2.y), u2h(bv.z)));
            __half2 h3 = h2exp(__hadd2(__floats2half2_rn(f3.x, f3.y), u2h(bv.w)));
            *(uint4*)(sP + tid * 72 + seg * 8) = make_uint4(h2u(h0), h2u(h1), h2u(h2), h2u(h3));
        }
        __syncthreads();

        // warp MMA
        int arow = (lane & 7) + ((lane >> 3) & 1) * 8;
        int akoff = (lane >> 4) * 8;
        int brow = lane & 7;
        int bkoff = ((lane >> 3) & 1) * 8;
#pragma unroll
        for (int ks = 0; ks < 4; ++ks) {
            int k0 = ks * 16;
            unsigned af[2][4];
#pragma unroll
            for (int mt = 0; mt < 2; ++mt) {
                uint32_t aaddr = sPb + ((q0 + mt * 16 + arow) * 72 + k0 + akoff) * 2;
                asm volatile("ldmatrix.sync.aligned.m8n8.x4.shared.b16 {%0,%1,%2,%3}, [%4];"
                             : "=r"(af[mt][0]), "=r"(af[mt][1]), "=r"(af[mt][2]), "=r"(af[mt][3])
                             : "r"(aaddr));
                // l = P @ ones   (one n8 mma per M-tile per k-step)
                asm volatile(
                    "mma.sync.aligned.m16n8k16.row.col.f32.f16.f16.f32 "
                    "{%0,%1,%2,%3}, {%4,%5,%6,%7}, {%8,%9}, {%0,%1,%2,%3};"
                    : "+f"(lfrag[mt][0]), "+f"(lfrag[mt][1]),
                      "+f"(lfrag[mt][2]), "+f"(lfrag[mt][3])
                    : "r"(af[mt][0]), "r"(af[mt][1]), "r"(af[mt][2]), "r"(af[mt][3]),
                      "r"(ONES), "r"(ONES));
            }
#pragma unroll
            for (int nb = 0; nb < 8; ++nb) {
                unsigned bf[2];
                uint32_t baddr = sVb + ((nb * 8 + brow) * 72 + k0 + bkoff) * 2;
                asm volatile("ldmatrix.sync.aligned.m8n8.x2.shared.b16 {%0,%1}, [%2];"
                             : "=r"(bf[0]), "=r"(bf[1]) : "r"(baddr));
#pragma unroll
                for (int mt = 0; mt < 2; ++mt) {
                    asm volatile(
                        "mma.sync.aligned.m16n8k16.row.col.f32.f16.f16.f32 "
                        "{%0,%1,%2,%3}, {%4,%5,%6,%7}, {%8,%9}, {%0,%1,%2,%3};"
                        : "+f"(acc[mt][nb][0]), "+f"(acc[mt][nb][1]),
                          "+f"(acc[mt][nb][2]), "+f"(acc[mt][nb][3])
                        : "r"(af[mt][0]), "r"(af[mt][1]), "r"(af[mt][2]), "r"(af[mt][3]),
                          "r"(bf[0]), "r"(bf[1]));
                }
            }
        }
    }

    // ---- epilogue: fragment scatter, normalize by l from ones-MMA ----
#pragma unroll
    for (int mt = 0; mt < 2; ++mt) {
        int rbase = q0 + mt * 16 + (lane >> 2);
        float linv[2] = {1.0f / lfrag[mt][0], 1.0f / lfrag[mt][2]};
#pragma unroll
        for (int hf = 0; hf < 2; ++hf) {
            int qr = rbase + hf * 8;
            float inv = linv[hf];
            int n2 = nt * 128 + qr;
            int tt = n2 >> 8, hy = (n2 >> 4) & 15, wx = n2 & 15;
#pragma unroll
            for (int nb = 0; nb < 8; ++nb) {
                int col = nb * 8 + (lane & 3) * 2;
                int dd = col >> 4, pp = col & 15;
                int y = hy * 4 + (pp >> 2);
                int xx = wx * 4 + (pp & 3);
                float* ob = out + ((size_t)((b * 128 + g * 4 + dd) * 4 + tt)) * 4096 + y * 64 + xx;
                ob[0] = acc[mt][nb][hf * 2 + 0] * inv;
                ob[1] = acc[mt][nb][hf * 2 + 1] * inv;
            }
        }
    }
}

// ---------------------------------------------------------------------------
extern "C" void kernel_launch(void* const* d_in, const int* in_sizes, int n_in,
                              void* d_out, int out_size) {
    const float* x   = (const float*)d_in[0];
    const float* Wq  = (const float*)d_in[1];
    const float* Wk  = (const float*)d_in[2];
    const float* Wv  = (const float*)d_in[3];
    const float* gqg = (const float*)d_in[4];
    const float* gqb = (const float*)d_in[5];
    const float* gkg = (const float*)d_in[6];
    const float* gkb = (const float*)d_in[7];
    const float* gvg = (const float*)d_in[8];
    const float* gvb = (const float*)d_in[9];
    const float* tab = (const float*)d_in[10];
    const int*   ri  = (const int*)d_in[11];
    float* out = (float*)d_out;

    cudaFuncSetAttribute(k_gnconst, cudaFuncAttributeMaxDynamicSharedMemorySize, 128 * 133 * 4);
    cudaFuncSetAttribute(k_attn, cudaFuncAttributeMaxDynamicSharedMemorySize, 44032);

    k_zero<<<32, 1024>>>();
    k_bias<<<512, 256>>>(tab, ri);
    k_pool<<<1024, 256>>>(x);
    k_gram<<<512, 256>>>(x);
    k_gnconst<<<192, 128, 128 * 133 * 4>>>(Wq, Wk, Wv, gqg, gqb, gkg, gkb, gvg, gvb);
    k_qkproj<<<64, 256>>>(Wq, Wk);
    k_vproj<<<128, 256>>>(x, Wv);
    k_attn<<<512, 128, 44032>>>(out);
}